// round 1
// baseline (speedup 1.0000x reference)
#include <cuda_runtime.h>

#define NN 50000
#define NE 1000000
#define D 64
#define R 8
#define ZCOLS 576   // R*D linear part + D self part

// Scratch (allocation-free rule: __device__ globals)
__device__ float g_deg[NN * R];
__device__ float g_z[(size_t)NN * ZCOLS];

// ---------------------------------------------------------------------------
__global__ void zero_deg_kernel() {
    int i = blockIdx.x * blockDim.x + threadIdx.x;
    if (i < NN * R) g_deg[i] = 0.0f;
}

__global__ void deg_kernel(const int* __restrict__ dst, const int* __restrict__ rel,
                           const float* __restrict__ w) {
    int e = blockIdx.x * blockDim.x + threadIdx.x;
    if (e < NE) atomicAdd(&g_deg[dst[e] * R + rel[e]], w[e]);
}

// ---------------------------------------------------------------------------
// z[n, r*64+j] = sum_k x[n,k] * W_linear[(r*64+k)*64 + j]   (r = 0..7)
// z[n, 512+j]  = sum_k x[n,k] * W_self[k*64 + j]
// BM=128 rows per block, 9 contiguous 64x64 B-tiles, X staged once (transposed).
#define BM 128
__global__ __launch_bounds__(256) void gemm_kernel(const float* __restrict__ x,
                                                   const float* __restrict__ Wlin,
                                                   const float* __restrict__ Wself) {
    __shared__ float Xs[64 * BM];   // Xs[k*BM + m]  (transposed, 32KB)
    __shared__ float Ws[64 * 64];   // Ws[k*64 + j]  (16KB)  -> 48KB total

    int t = threadIdx.x;
    int m_base = blockIdx.x * BM;

    // Load X tile (coalesced), store transposed. One time per block.
#pragma unroll
    for (int i = 0; i < 8; i++) {
        int f  = i * 256 + t;        // 2048 float4s = 128 rows x 16
        int m  = f >> 4;
        int k4 = (f & 15) * 4;
        float4 v = make_float4(0.f, 0.f, 0.f, 0.f);
        int gm = m_base + m;
        if (gm < NN) v = *(const float4*)&x[gm * D + k4];
        Xs[(k4 + 0) * BM + m] = v.x;
        Xs[(k4 + 1) * BM + m] = v.y;
        Xs[(k4 + 2) * BM + m] = v.z;
        Xs[(k4 + 3) * BM + m] = v.w;
    }

    int tx = t & 15, ty = t >> 4;   // 16 x 16 thread grid
    int m0 = ty * 8;                // 8 rows per thread
    int j0 = tx * 4;                // 4 cols per thread

    for (int r = 0; r < 9; r++) {
        const float* B = (r < 8) ? (Wlin + r * 4096) : Wself;
        __syncthreads();            // protect Ws reuse (and Xs on first iter)
#pragma unroll
        for (int i = 0; i < 4; i++) {
            int f = i * 256 + t;    // 1024 float4s
            ((float4*)Ws)[f] = ((const float4*)B)[f];
        }
        __syncthreads();

        float acc[8][4];
#pragma unroll
        for (int i = 0; i < 8; i++)
#pragma unroll
            for (int j = 0; j < 4; j++) acc[i][j] = 0.f;

#pragma unroll 8
        for (int k = 0; k < 64; k++) {
            float4 a0 = *(const float4*)&Xs[k * BM + m0];
            float4 a1 = *(const float4*)&Xs[k * BM + m0 + 4];
            float4 b  = *(const float4*)&Ws[k * 64 + j0];
            float a[8] = {a0.x, a0.y, a0.z, a0.w, a1.x, a1.y, a1.z, a1.w};
            float bb[4] = {b.x, b.y, b.z, b.w};
#pragma unroll
            for (int i = 0; i < 8; i++)
#pragma unroll
                for (int j = 0; j < 4; j++) acc[i][j] += a[i] * bb[j];
        }

#pragma unroll
        for (int i = 0; i < 8; i++) {
            int gm = m_base + m0 + i;
            if (gm < NN) {
                float4 v = make_float4(acc[i][0], acc[i][1], acc[i][2], acc[i][3]);
                *(float4*)&g_z[(size_t)gm * ZCOLS + r * 64 + j0] = v;
            }
        }
    }
}

// ---------------------------------------------------------------------------
// out[n, j] = z[n, 512+j] + b_linear[j] + b_self[j]
__global__ void init_out_kernel(float* __restrict__ out,
                                const float* __restrict__ b_lin,
                                const float* __restrict__ b_self) {
    int i = blockIdx.x * blockDim.x + threadIdx.x;
    if (i < NN * D) {
        int n = i >> 6, j = i & 63;
        out[i] = g_z[(size_t)n * ZCOLS + 512 + j] + b_lin[j] + b_self[j];
    }
}

// ---------------------------------------------------------------------------
__device__ __forceinline__ void red_add_f32x4(float* addr, float4 v) {
    asm volatile("red.global.add.v4.f32 [%0], {%1, %2, %3, %4};"
                 :: "l"(addr), "f"(v.x), "f"(v.y), "f"(v.z), "f"(v.w)
                 : "memory");
}

// 8 threads per edge; thread q handles floats [q*8, q*8+8)
__global__ __launch_bounds__(256) void scatter_kernel(const int* __restrict__ src,
                                                      const int* __restrict__ dst,
                                                      const int* __restrict__ rel,
                                                      const float* __restrict__ w,
                                                      float* __restrict__ out) {
    unsigned gid = blockIdx.x * blockDim.x + threadIdx.x;
    unsigned e = gid >> 3;
    if (e >= NE) return;
    int q = (gid & 7) * 8;

    int s  = src[e];
    int d_ = dst[e];
    int r_ = rel[e];
    float ew = w[e] / g_deg[d_ * R + r_];

    const float* zp = &g_z[(size_t)s * ZCOLS + r_ * 64 + q];
    float4 v0 = *(const float4*)zp;
    float4 v1 = *(const float4*)(zp + 4);
    v0.x *= ew; v0.y *= ew; v0.z *= ew; v0.w *= ew;
    v1.x *= ew; v1.y *= ew; v1.z *= ew; v1.w *= ew;

    float* op = &out[d_ * D + q];
    red_add_f32x4(op, v0);
    red_add_f32x4(op + 4, v1);
}

// ---------------------------------------------------------------------------
__global__ void relu_kernel(float* __restrict__ out) {
    int i = blockIdx.x * blockDim.x + threadIdx.x;
    if (i < NN * D) out[i] = fmaxf(out[i], 0.0f);
}

// ---------------------------------------------------------------------------
extern "C" void kernel_launch(void* const* d_in, const int* in_sizes, int n_in,
                              void* d_out, int out_size) {
    const float* x      = (const float*)d_in[0];
    const int*   e_src  = (const int*)d_in[1];
    const int*   e_dst  = (const int*)d_in[2];
    const int*   e_rel  = (const int*)d_in[3];
    const float* e_w    = (const float*)d_in[4];
    const float* W_lin  = (const float*)d_in[5];
    const float* b_lin  = (const float*)d_in[6];
    const float* W_self = (const float*)d_in[7];
    const float* b_self = (const float*)d_in[8];
    float* out = (float*)d_out;

    zero_deg_kernel<<<(NN * R + 255) / 256, 256>>>();
    deg_kernel<<<(NE + 255) / 256, 256>>>(e_dst, e_rel, e_w);
    gemm_kernel<<<(NN + BM - 1) / BM, 256>>>(x, W_lin, W_self);
    init_out_kernel<<<(NN * D + 255) / 256, 256>>>(out, b_lin, b_self);
    scatter_kernel<<<(NE * 8 + 255) / 256, 256>>>(e_src, e_dst, e_rel, e_w, out);
    relu_kernel<<<(NN * D + 255) / 256, 256>>>(out);
}

// round 3
// speedup vs baseline: 1.2032x; 1.2032x over previous
#include <cuda_runtime.h>
#include <cuda_bf16.h>
#include <cstdint>

#define NN 50000
#define NE 1000000
#define DD 64
#define RR 8
#define ZC 512          // z holds only the 8 relation tiles; self part goes straight to out

// Scratch (allocation-free rule)
__device__ float g_deg[NN * RR];
__device__ float g_z[(size_t)NN * ZC];

// ---------------------------------------------------------------------------
__device__ __forceinline__ uint32_t smem_u32(const void* p) {
    uint32_t a;
    asm("{ .reg .u64 t; cvta.to.shared.u64 t, %1; cvt.u32.u64 %0, t; }" : "=r"(a) : "l"(p));
    return a;
}

__device__ __forceinline__ void ldsm_x4(uint32_t* r, uint32_t addr) {
    asm volatile("ldmatrix.sync.aligned.m8n8.x4.shared.b16 {%0,%1,%2,%3}, [%4];"
                 : "=r"(r[0]), "=r"(r[1]), "=r"(r[2]), "=r"(r[3]) : "r"(addr));
}
__device__ __forceinline__ void ldsm_x4_t(uint32_t* r, uint32_t addr) {
    asm volatile("ldmatrix.sync.aligned.m8n8.x4.trans.shared.b16 {%0,%1,%2,%3}, [%4];"
                 : "=r"(r[0]), "=r"(r[1]), "=r"(r[2]), "=r"(r[3]) : "r"(addr));
}
__device__ __forceinline__ void mma_bf16(float* c, const uint32_t* a, uint32_t b0, uint32_t b1) {
    asm volatile("mma.sync.aligned.m16n8k16.row.col.f32.bf16.bf16.f32 "
                 "{%0,%1,%2,%3}, {%4,%5,%6,%7}, {%8,%9}, {%0,%1,%2,%3};"
                 : "+f"(c[0]), "+f"(c[1]), "+f"(c[2]), "+f"(c[3])
                 : "r"(a[0]), "r"(a[1]), "r"(a[2]), "r"(a[3]), "r"(b0), "r"(b1));
}

// ---------------------------------------------------------------------------
__global__ void zero_deg_kernel() {
    int i = blockIdx.x * blockDim.x + threadIdx.x;
    if (i < NN * RR) g_deg[i] = 0.0f;
}

__global__ void deg_kernel(const int* __restrict__ dst, const int* __restrict__ rel,
                           const float* __restrict__ w) {
    int e = blockIdx.x * blockDim.x + threadIdx.x;
    if (e < NE) atomicAdd(&g_deg[dst[e] * RR + rel[e]], w[e]);
}

// ---------------------------------------------------------------------------
// Tensor-core GEMM via mma.sync bf16 split (plain sm_80-class ISA).
//   z[m, r*64+j] = sum_k x[m,k] * Wlin[(r*64+k)*64+j]   r=0..7
//   out[m, j]    = sum_k x[m,k] * Wself[k*64+j] + b_lin[j] + b_self[j]
#define AP 72     // padded bf16 row stride (144 B: 16B-aligned, conflict-free ldmatrix)
#define BP 72
#define SM_BIAS 0                       // 64 floats
#define SM_AH   256                     // 128 x AP bf16 = 18432 B
#define SM_AL   (SM_AH + 128 * AP * 2)
#define SM_BH   (SM_AL + 128 * AP * 2)  // 64 x BP bf16 = 9216 B
#define SM_BL   (SM_BH + 64 * BP * 2)
#define SMEM_TOTAL (SM_BL + 64 * BP * 2)  // 55552 B

__global__ __launch_bounds__(256) void gemm_kernel(const float* __restrict__ x,
                                                   const float* __restrict__ Wlin,
                                                   const float* __restrict__ Wself,
                                                   const float* __restrict__ b_lin,
                                                   const float* __restrict__ b_self,
                                                   float* __restrict__ out) {
    extern __shared__ char smem[];
    uint32_t sb = smem_u32(smem);
    int t = threadIdx.x, wid = t >> 5, lid = t & 31;
    int m_base = blockIdx.x * 128;

    float* bias = (float*)(smem + SM_BIAS);
    if (t < 64) bias[t] = b_lin[t] + b_self[t];

    // --- Stage A: 128 x 64 fp32 -> hi/lo bf16 ---
    for (int f = t; f < 128 * 32; f += 256) {         // f indexes float2
        int m = f >> 5, kp = f & 31;
        float2 v = make_float2(0.f, 0.f);
        int gm = m_base + m;
        if (gm < NN) v = *(const float2*)&x[gm * DD + kp * 2];
        __nv_bfloat16 hx = __float2bfloat16_rn(v.x);
        __nv_bfloat16 hy = __float2bfloat16_rn(v.y);
        __nv_bfloat16 lx = __float2bfloat16_rn(v.x - __bfloat162float(hx));
        __nv_bfloat16 ly = __float2bfloat16_rn(v.y - __bfloat162float(hy));
        uint32_t hp = (uint32_t)__bfloat16_as_ushort(hx) | ((uint32_t)__bfloat16_as_ushort(hy) << 16);
        uint32_t lp = (uint32_t)__bfloat16_as_ushort(lx) | ((uint32_t)__bfloat16_as_ushort(ly) << 16);
        uint32_t boff = (uint32_t)(m * AP + kp * 2) * 2;
        *(uint32_t*)(smem + SM_AH + boff) = hp;
        *(uint32_t*)(smem + SM_AL + boff) = lp;
    }
    __syncthreads();

    // --- Load A fragments once (persist across all 9 B tiles) ---
    // m16k16 frag: matrix0 rows0-7/klow, m1 rows8-15/klow, m2 rows0-7/khigh, m3 rows8-15/khigh
    uint32_t a_h[4][4], a_l[4][4];
    {
        int arow = wid * 16 + (lid & 7) + ((lid >> 3) & 1) * 8;
        int acol = (lid >> 4) * 8;
#pragma unroll
        for (int kk = 0; kk < 4; kk++) {
            uint32_t off = (uint32_t)(arow * AP + kk * 16 + acol) * 2;
            ldsm_x4(a_h[kk], sb + SM_AH + off);
            ldsm_x4(a_l[kk], sb + SM_AL + off);
        }
    }

    // --- Loop over 9 B tiles ---
    for (int g = 0; g < 9; g++) {
        __syncthreads();    // previous tile's compute done reading B smem
        for (int f = t; f < 64 * 32; f += 256) {      // f indexes float2
            int k = f >> 5, jp = f & 31;
            float2 v = (g < 8) ? *(const float2*)&Wlin[(g * 64 + k) * 64 + jp * 2]
                               : *(const float2*)&Wself[k * 64 + jp * 2];
            __nv_bfloat16 hx = __float2bfloat16_rn(v.x);
            __nv_bfloat16 hy = __float2bfloat16_rn(v.y);
            __nv_bfloat16 lx = __float2bfloat16_rn(v.x - __bfloat162float(hx));
            __nv_bfloat16 ly = __float2bfloat16_rn(v.y - __bfloat162float(hy));
            uint32_t hp = (uint32_t)__bfloat16_as_ushort(hx) | ((uint32_t)__bfloat16_as_ushort(hy) << 16);
            uint32_t lp = (uint32_t)__bfloat16_as_ushort(lx) | ((uint32_t)__bfloat16_as_ushort(ly) << 16);
            uint32_t boff = (uint32_t)(k * BP + jp * 2) * 2;
            *(uint32_t*)(smem + SM_BH + boff) = hp;
            *(uint32_t*)(smem + SM_BL + boff) = lp;
        }
        __syncthreads();

        float acc[8][4];
#pragma unroll
        for (int n = 0; n < 8; n++)
#pragma unroll
            for (int q = 0; q < 4; q++) acc[n][q] = 0.f;

        // B frag (k16 x n8, col-major) via ldmatrix.x4.trans from row-major B[k][j].
        // x4 covers two n-tiles: m0=klow/n, m1=khigh/n, m2=klow/n+8, m3=khigh/n+8
        int brow_i = (lid & 7) + ((lid >> 3) & 1) * 8;   // row within k16 chunk
        int bcol_i = (lid >> 4) * 8;                     // 0 or 8 (second n-tile)
#pragma unroll
        for (int kk = 0; kk < 4; kk++) {
            uint32_t bfh[16], bfl[16];
#pragma unroll
            for (int tp = 0; tp < 4; tp++) {
                uint32_t off = (uint32_t)((kk * 16 + brow_i) * BP + tp * 16 + bcol_i) * 2;
                ldsm_x4_t(bfh + tp * 4, sb + SM_BH + off);
                ldsm_x4_t(bfl + tp * 4, sb + SM_BL + off);
            }
#pragma unroll
            for (int n = 0; n < 8; n++) {
                int base = (n >> 1) * 4 + (n & 1) * 2;
                uint32_t b0h = bfh[base], b1h = bfh[base + 1];
                uint32_t b0l = bfl[base], b1l = bfl[base + 1];
                mma_bf16(acc[n], a_h[kk], b0h, b1h);
                mma_bf16(acc[n], a_h[kk], b0l, b1l);
                mma_bf16(acc[n], a_l[kk], b0h, b1h);
            }
        }

        // Writeout. Acc frag: c0,c1 at row l>>2, cols (l&3)*2..+1; c2,c3 at row+8.
        int r0 = m_base + wid * 16 + (lid >> 2);
        int r1 = r0 + 8;
        int c0 = (lid & 3) * 2;
        if (g < 8) {
#pragma unroll
            for (int n = 0; n < 8; n++) {
                int col = g * 64 + n * 8 + c0;
                if (r0 < NN) *(float2*)&g_z[(size_t)r0 * ZC + col] = make_float2(acc[n][0], acc[n][1]);
                if (r1 < NN) *(float2*)&g_z[(size_t)r1 * ZC + col] = make_float2(acc[n][2], acc[n][3]);
            }
        } else {
#pragma unroll
            for (int n = 0; n < 8; n++) {
                int col = n * 8 + c0;
                float2 bs = *(float2*)&bias[col];
                if (r0 < NN) *(float2*)&out[r0 * DD + col] = make_float2(acc[n][0] + bs.x, acc[n][1] + bs.y);
                if (r1 < NN) *(float2*)&out[r1 * DD + col] = make_float2(acc[n][2] + bs.x, acc[n][3] + bs.y);
            }
        }
    }
}

// ---------------------------------------------------------------------------
__device__ __forceinline__ void red_add_f32x4(float* addr, float4 v) {
    asm volatile("red.global.add.v4.f32 [%0], {%1, %2, %3, %4};"
                 :: "l"(addr), "f"(v.x), "f"(v.y), "f"(v.z), "f"(v.w)
                 : "memory");
}

// 8 threads per edge; thread q handles floats [q*8, q*8+8)
__global__ __launch_bounds__(256) void scatter_kernel(const int* __restrict__ src,
                                                      const int* __restrict__ dst,
                                                      const int* __restrict__ rel,
                                                      const float* __restrict__ w,
                                                      float* __restrict__ out) {
    unsigned gid = blockIdx.x * blockDim.x + threadIdx.x;
    unsigned e = gid >> 3;
    if (e >= NE) return;
    int q = (gid & 7) * 8;

    int s  = src[e];
    int d_ = dst[e];
    int r_ = rel[e];
    float ew = w[e] / g_deg[d_ * RR + r_];

    const float* zp = &g_z[(size_t)s * ZC + r_ * 64 + q];
    float4 v0 = *(const float4*)zp;
    float4 v1 = *(const float4*)(zp + 4);
    v0.x *= ew; v0.y *= ew; v0.z *= ew; v0.w *= ew;
    v1.x *= ew; v1.y *= ew; v1.z *= ew; v1.w *= ew;

    float* op = &out[d_ * DD + q];
    red_add_f32x4(op, v0);
    red_add_f32x4(op + 4, v1);
}

// ---------------------------------------------------------------------------
__global__ void relu_kernel(float* __restrict__ out) {
    int i = blockIdx.x * blockDim.x + threadIdx.x;
    if (i < NN * DD) out[i] = fmaxf(out[i], 0.0f);
}

// ---------------------------------------------------------------------------
extern "C" void kernel_launch(void* const* d_in, const int* in_sizes, int n_in,
                              void* d_out, int out_size) {
    const float* x      = (const float*)d_in[0];
    const int*   e_src  = (const int*)d_in[1];
    const int*   e_dst  = (const int*)d_in[2];
    const int*   e_rel  = (const int*)d_in[3];
    const float* e_w    = (const float*)d_in[4];
    const float* W_lin  = (const float*)d_in[5];
    const float* b_lin  = (const float*)d_in[6];
    const float* W_self = (const float*)d_in[7];
    const float* b_self = (const float*)d_in[8];
    float* out = (float*)d_out;

    cudaFuncSetAttribute(gemm_kernel, cudaFuncAttributeMaxDynamicSharedMemorySize, SMEM_TOTAL);

    zero_deg_kernel<<<(NN * RR + 255) / 256, 256>>>();
    deg_kernel<<<(NE + 255) / 256, 256>>>(e_dst, e_rel, e_w);
    gemm_kernel<<<(NN + 127) / 128, 256, SMEM_TOTAL>>>(x, W_lin, W_self, b_lin, b_self, out);
    scatter_kernel<<<(NE * 8 + 255) / 256, 256>>>(e_src, e_dst, e_rel, e_w, out);
    relu_kernel<<<(NN * DD + 255) / 256, 256>>>(out);
}

// round 4
// speedup vs baseline: 1.2854x; 1.0684x over previous
#include <cuda_runtime.h>
#include <cuda_bf16.h>
#include <cstdint>

#define NN 50000
#define NE 1000000
#define DD 64
#define RR 8
#define ZC 512

// Scratch (allocation-free rule)
__device__ float g_z[(size_t)NN * ZC];
__device__ __nv_bfloat16 g_Wh[576 * 64];
__device__ __nv_bfloat16 g_Wl[576 * 64];
__device__ int   g_cnt[NN];
__device__ int   g_rs[NN + 1];     // CSR row starts (exclusive prefix)
__device__ int   g_cur[NN];        // fill cursors
__device__ int   g_part[64];       // scan block partials
__device__ int   g_esr[NE];        // sorted: src*8+rel
__device__ float g_ew[NE];         // sorted: weight

// ---------------------------------------------------------------------------
__device__ __forceinline__ uint32_t smem_u32(const void* p) {
    uint32_t a;
    asm("{ .reg .u64 t; cvta.to.shared.u64 t, %1; cvt.u32.u64 %0, t; }" : "=r"(a) : "l"(p));
    return a;
}
__device__ __forceinline__ void ldsm_x4(uint32_t* r, uint32_t addr) {
    asm volatile("ldmatrix.sync.aligned.m8n8.x4.shared.b16 {%0,%1,%2,%3}, [%4];"
                 : "=r"(r[0]), "=r"(r[1]), "=r"(r[2]), "=r"(r[3]) : "r"(addr));
}
__device__ __forceinline__ void ldsm_x4_t(uint32_t* r, uint32_t addr) {
    asm volatile("ldmatrix.sync.aligned.m8n8.x4.trans.shared.b16 {%0,%1,%2,%3}, [%4];"
                 : "=r"(r[0]), "=r"(r[1]), "=r"(r[2]), "=r"(r[3]) : "r"(addr));
}
__device__ __forceinline__ void mma_bf16(float* c, const uint32_t* a, uint32_t b0, uint32_t b1) {
    asm volatile("mma.sync.aligned.m16n8k16.row.col.f32.bf16.bf16.f32 "
                 "{%0,%1,%2,%3}, {%4,%5,%6,%7}, {%8,%9}, {%0,%1,%2,%3};"
                 : "+f"(c[0]), "+f"(c[1]), "+f"(c[2]), "+f"(c[3])
                 : "r"(a[0]), "r"(a[1]), "r"(a[2]), "r"(a[3]), "r"(b0), "r"(b1));
}

// ---------------------------------------------------------------------------
// Weight precompute: one-time fp32 -> bf16 hi/lo split of [Wlin ; Wself]
__global__ void prep_w_kernel(const float* __restrict__ Wlin, const float* __restrict__ Wself) {
    int idx = blockIdx.x * blockDim.x + threadIdx.x;   // 36864
    if (idx >= 576 * 64) return;
    float v = (idx < 512 * 64) ? Wlin[idx] : Wself[idx - 512 * 64];
    __nv_bfloat16 h = __float2bfloat16_rn(v);
    __nv_bfloat16 l = __float2bfloat16_rn(v - __bfloat162float(h));
    g_Wh[idx] = h; g_Wl[idx] = l;
}

// ---------------------------------------------------------------------------
// CSR build
__global__ void zero_cnt_kernel() {
    int i = blockIdx.x * blockDim.x + threadIdx.x;
    if (i < NN) g_cnt[i] = 0;
}
__global__ void hist_kernel(const int* __restrict__ dst) {
    int e = blockIdx.x * blockDim.x + threadIdx.x;
    if (e < NE) atomicAdd(&g_cnt[dst[e]], 1);
}
__global__ void scan1_kernel() {
    __shared__ int s[1024];
    int tid = threadIdx.x;
    int i = blockIdx.x * 1024 + tid;
    int v = (i < NN) ? g_cnt[i] : 0;
    s[tid] = v;
    __syncthreads();
    for (int off = 1; off < 1024; off <<= 1) {
        int t = (tid >= off) ? s[tid - off] : 0;
        __syncthreads();
        s[tid] += t;
        __syncthreads();
    }
    if (i < NN) g_rs[i] = s[tid] - v;          // exclusive within block
    if (tid == 1023) g_part[blockIdx.x] = s[1023];
}
__global__ void scan2_kernel(int nblk) {
    if (threadIdx.x == 0 && blockIdx.x == 0) {
        int run = 0;
        for (int b = 0; b < nblk; b++) { int t = g_part[b]; g_part[b] = run; run += t; }
    }
}
__global__ void scan3_kernel() {
    int tid = threadIdx.x;
    int i = blockIdx.x * 1024 + tid;
    if (i < NN) {
        int v = g_rs[i] + g_part[blockIdx.x];
        g_rs[i] = v;
        g_cur[i] = v;
    }
    if (i == 0) g_rs[NN] = NE;
}
__global__ void fill_kernel(const int* __restrict__ src, const int* __restrict__ dst,
                            const int* __restrict__ rel, const float* __restrict__ w) {
    int e = blockIdx.x * blockDim.x + threadIdx.x;
    if (e >= NE) return;
    int d = dst[e];
    int pos = atomicAdd(&g_cur[d], 1);
    g_esr[pos] = src[e] * 8 + rel[e];
    g_ew[pos]  = w[e];
}

// ---------------------------------------------------------------------------
// Tensor-core GEMM (mma.sync bf16 split). B staged as raw bf16 copies.
#define AP 72
#define BP 72
#define SM_BIAS 0
#define SM_AH   256
#define SM_AL   (SM_AH + 128 * AP * 2)
#define SM_BH   (SM_AL + 128 * AP * 2)
#define SM_BL   (SM_BH + 64 * BP * 2)
#define SMEM_TOTAL (SM_BL + 64 * BP * 2)   // 55552 B

__global__ __launch_bounds__(256) void gemm_kernel(const float* __restrict__ x,
                                                   const float* __restrict__ b_lin,
                                                   const float* __restrict__ b_self,
                                                   float* __restrict__ out) {
    extern __shared__ char smem[];
    uint32_t sb = smem_u32(smem);
    int t = threadIdx.x, wid = t >> 5, lid = t & 31;
    int m_base = blockIdx.x * 128;

    float* bias = (float*)(smem + SM_BIAS);
    if (t < 64) bias[t] = b_lin[t] + b_self[t];

    // Stage A: 128x64 fp32 -> hi/lo bf16
    for (int f = t; f < 128 * 32; f += 256) {
        int m = f >> 5, kp = f & 31;
        float2 v = make_float2(0.f, 0.f);
        int gm = m_base + m;
        if (gm < NN) v = *(const float2*)&x[gm * DD + kp * 2];
        __nv_bfloat16 hx = __float2bfloat16_rn(v.x);
        __nv_bfloat16 hy = __float2bfloat16_rn(v.y);
        __nv_bfloat16 lx = __float2bfloat16_rn(v.x - __bfloat162float(hx));
        __nv_bfloat16 ly = __float2bfloat16_rn(v.y - __bfloat162float(hy));
        uint32_t hp = (uint32_t)__bfloat16_as_ushort(hx) | ((uint32_t)__bfloat16_as_ushort(hy) << 16);
        uint32_t lp = (uint32_t)__bfloat16_as_ushort(lx) | ((uint32_t)__bfloat16_as_ushort(ly) << 16);
        uint32_t boff = (uint32_t)(m * AP + kp * 2) * 2;
        *(uint32_t*)(smem + SM_AH + boff) = hp;
        *(uint32_t*)(smem + SM_AL + boff) = lp;
    }
    __syncthreads();

    // A fragments persist across all 9 tiles
    uint32_t a_h[4][4], a_l[4][4];
    {
        int arow = wid * 16 + (lid & 7) + ((lid >> 3) & 1) * 8;
        int acol = (lid >> 4) * 8;
#pragma unroll
        for (int kk = 0; kk < 4; kk++) {
            uint32_t off = (uint32_t)(arow * AP + kk * 16 + acol) * 2;
            ldsm_x4(a_h[kk], sb + SM_AH + off);
            ldsm_x4(a_l[kk], sb + SM_AL + off);
        }
    }

    for (int g = 0; g < 9; g++) {
        __syncthreads();
        // Stage B: raw uint4 copies of precomputed bf16 (no conversion math)
        for (int f = t; f < 64 * 8; f += 256) {
            int k = f >> 3, jc = f & 7;
            uint4 vh = *(const uint4*)&g_Wh[(g * 64 + k) * 64 + jc * 8];
            uint4 vl = *(const uint4*)&g_Wl[(g * 64 + k) * 64 + jc * 8];
            uint32_t boff = (uint32_t)(k * BP + jc * 8) * 2;
            *(uint4*)(smem + SM_BH + boff) = vh;
            *(uint4*)(smem + SM_BL + boff) = vl;
        }
        __syncthreads();

        float acc[8][4];
#pragma unroll
        for (int n = 0; n < 8; n++)
#pragma unroll
            for (int q = 0; q < 4; q++) acc[n][q] = 0.f;

        int brow_i = (lid & 7) + ((lid >> 3) & 1) * 8;
        int bcol_i = (lid >> 4) * 8;
#pragma unroll
        for (int kk = 0; kk < 4; kk++) {
            uint32_t bfh[16], bfl[16];
#pragma unroll
            for (int tp = 0; tp < 4; tp++) {
                uint32_t off = (uint32_t)((kk * 16 + brow_i) * BP + tp * 16 + bcol_i) * 2;
                ldsm_x4_t(bfh + tp * 4, sb + SM_BH + off);
                ldsm_x4_t(bfl + tp * 4, sb + SM_BL + off);
            }
#pragma unroll
            for (int n = 0; n < 8; n++) {
                int base = (n >> 1) * 4 + (n & 1) * 2;
                mma_bf16(acc[n], a_h[kk], bfh[base], bfh[base + 1]);
                mma_bf16(acc[n], a_h[kk], bfl[base], bfl[base + 1]);
                mma_bf16(acc[n], a_l[kk], bfh[base], bfh[base + 1]);
            }
        }

        int r0 = m_base + wid * 16 + (lid >> 2);
        int r1 = r0 + 8;
        int c0 = (lid & 3) * 2;
        if (g < 8) {
#pragma unroll
            for (int n = 0; n < 8; n++) {
                int col = g * 64 + n * 8 + c0;
                if (r0 < NN) *(float2*)&g_z[(size_t)r0 * ZC + col] = make_float2(acc[n][0], acc[n][1]);
                if (r1 < NN) *(float2*)&g_z[(size_t)r1 * ZC + col] = make_float2(acc[n][2], acc[n][3]);
            }
        } else {
#pragma unroll
            for (int n = 0; n < 8; n++) {
                int col = n * 8 + c0;
                float2 bs = *(float2*)&bias[col];
                if (r0 < NN) *(float2*)&out[r0 * DD + col] = make_float2(acc[n][0] + bs.x, acc[n][1] + bs.y);
                if (r1 < NN) *(float2*)&out[r1 * DD + col] = make_float2(acc[n][2] + bs.x, acc[n][3] + bs.y);
            }
        }
    }
}

// ---------------------------------------------------------------------------
// Gather: one warp per destination node. Pass 1: per-relation degree in-warp.
// Pass 2: accumulate (w/deg)*z[src,rel] in registers. Epilogue fuses +self and relu.
__global__ __launch_bounds__(256) void gather_kernel(float* __restrict__ out) {
    __shared__ float sinv[8][8];
    int t = threadIdx.x, wid = t >> 5, lid = t & 31;
    int node = blockIdx.x * 8 + wid;        // grid = 6250, exact
    int beg = g_rs[node], end = g_rs[node + 1];

    // Pass 1: degrees per relation
    float deg8[8];
#pragma unroll
    for (int q = 0; q < 8; q++) deg8[q] = 0.f;
    for (int i = beg + lid; i < end; i += 32) {
        int r = g_esr[i] & 7;
        float w = g_ew[i];
#pragma unroll
        for (int q = 0; q < 8; q++) if (r == q) deg8[q] += w;
    }
#pragma unroll
    for (int q = 0; q < 8; q++)
#pragma unroll
        for (int o = 16; o; o >>= 1) deg8[q] += __shfl_xor_sync(0xFFFFFFFFu, deg8[q], o);
    if (lid == 0) {
#pragma unroll
        for (int q = 0; q < 8; q++) sinv[wid][q] = 1.0f / deg8[q];
    }
    __syncwarp();

    // Pass 2: accumulate messages (2 output floats per lane), unroll by 2
    float a0 = 0.f, a1 = 0.f;
    int i = beg;
    for (; i + 1 < end; i += 2) {
        int sr0 = g_esr[i], sr1 = g_esr[i + 1];
        float w0 = g_ew[i], w1 = g_ew[i + 1];
        float2 z0 = *(const float2*)&g_z[(size_t)sr0 * 64 + lid * 2];
        float2 z1 = *(const float2*)&g_z[(size_t)sr1 * 64 + lid * 2];
        float v0 = w0 * sinv[wid][sr0 & 7];
        float v1 = w1 * sinv[wid][sr1 & 7];
        a0 += v0 * z0.x + v1 * z1.x;
        a1 += v0 * z0.y + v1 * z1.y;
    }
    if (i < end) {
        int sr0 = g_esr[i];
        float v0 = g_ew[i] * sinv[wid][sr0 & 7];
        float2 z0 = *(const float2*)&g_z[(size_t)sr0 * 64 + lid * 2];
        a0 += v0 * z0.x;
        a1 += v0 * z0.y;
    }

    float2 o = *(float2*)&out[node * DD + lid * 2];
    o.x = fmaxf(o.x + a0, 0.f);
    o.y = fmaxf(o.y + a1, 0.f);
    *(float2*)&out[node * DD + lid * 2] = o;
}

// ---------------------------------------------------------------------------
extern "C" void kernel_launch(void* const* d_in, const int* in_sizes, int n_in,
                              void* d_out, int out_size) {
    const float* x      = (const float*)d_in[0];
    const int*   e_src  = (const int*)d_in[1];
    const int*   e_dst  = (const int*)d_in[2];
    const int*   e_rel  = (const int*)d_in[3];
    const float* e_w    = (const float*)d_in[4];
    const float* W_lin  = (const float*)d_in[5];
    const float* b_lin  = (const float*)d_in[6];
    const float* W_self = (const float*)d_in[7];
    const float* b_self = (const float*)d_in[8];
    float* out = (float*)d_out;

    cudaFuncSetAttribute(gemm_kernel, cudaFuncAttributeMaxDynamicSharedMemorySize, SMEM_TOTAL);

    const int SCAN_BLKS = (NN + 1023) / 1024;   // 49
    prep_w_kernel<<<(576 * 64 + 255) / 256, 256>>>(W_lin, W_self);
    zero_cnt_kernel<<<(NN + 255) / 256, 256>>>();
    hist_kernel<<<(NE + 255) / 256, 256>>>(e_dst);
    scan1_kernel<<<SCAN_BLKS, 1024>>>();
    scan2_kernel<<<1, 32>>>(SCAN_BLKS);
    scan3_kernel<<<SCAN_BLKS, 1024>>>();
    fill_kernel<<<(NE + 255) / 256, 256>>>(e_src, e_dst, e_rel, e_w);
    gemm_kernel<<<(NN + 127) / 128, 256, SMEM_TOTAL>>>(x, b_lin, b_self, out);
    gather_kernel<<<NN / 8, 256>>>(out);
}

// round 5
// speedup vs baseline: 1.3937x; 1.0842x over previous
#include <cuda_runtime.h>
#include <cuda_bf16.h>
#include <cstdint>

#define NN 50000
#define NE 1000000
#define DD 64
#define RR 8
#define ZC 512

// Scratch (allocation-free rule)
__device__ __nv_bfloat16 g_z[(size_t)NN * ZC];   // 51.2 MB, L2-resident
__device__ __nv_bfloat16 g_Wh[576 * 64];
__device__ __nv_bfloat16 g_Wl[576 * 64];
__device__ int  g_cnt[NN];
__device__ int  g_rs[NN + 1];
__device__ int  g_cur[NN];
__device__ int  g_part[64];
__device__ int2 g_ep[NE];        // packed: {src*8+rel, w bits}

// ---------------------------------------------------------------------------
__device__ __forceinline__ uint32_t smem_u32(const void* p) {
    uint32_t a;
    asm("{ .reg .u64 t; cvta.to.shared.u64 t, %1; cvt.u32.u64 %0, t; }" : "=r"(a) : "l"(p));
    return a;
}
__device__ __forceinline__ void ldsm_x4(uint32_t* r, uint32_t addr) {
    asm volatile("ldmatrix.sync.aligned.m8n8.x4.shared.b16 {%0,%1,%2,%3}, [%4];"
                 : "=r"(r[0]), "=r"(r[1]), "=r"(r[2]), "=r"(r[3]) : "r"(addr));
}
__device__ __forceinline__ void ldsm_x4_t(uint32_t* r, uint32_t addr) {
    asm volatile("ldmatrix.sync.aligned.m8n8.x4.trans.shared.b16 {%0,%1,%2,%3}, [%4];"
                 : "=r"(r[0]), "=r"(r[1]), "=r"(r[2]), "=r"(r[3]) : "r"(addr));
}
__device__ __forceinline__ void mma_bf16(float* c, const uint32_t* a, uint32_t b0, uint32_t b1) {
    asm volatile("mma.sync.aligned.m16n8k16.row.col.f32.bf16.bf16.f32 "
                 "{%0,%1,%2,%3}, {%4,%5,%6,%7}, {%8,%9}, {%0,%1,%2,%3};"
                 : "+f"(c[0]), "+f"(c[1]), "+f"(c[2]), "+f"(c[3])
                 : "r"(a[0]), "r"(a[1]), "r"(a[2]), "r"(a[3]), "r"(b0), "r"(b1));
}
__device__ __forceinline__ int warp_iscan(int v, int lane) {
#pragma unroll
    for (int off = 1; off < 32; off <<= 1) {
        int t = __shfl_up_sync(0xFFFFFFFFu, v, off);
        if (lane >= off) v += t;
    }
    return v;
}

// ---------------------------------------------------------------------------
__global__ void prep_w_kernel(const float* __restrict__ Wlin, const float* __restrict__ Wself) {
    int idx = blockIdx.x * blockDim.x + threadIdx.x;
    if (idx >= 576 * 64) return;
    float v = (idx < 512 * 64) ? Wlin[idx] : Wself[idx - 512 * 64];
    __nv_bfloat16 h = __float2bfloat16_rn(v);
    __nv_bfloat16 l = __float2bfloat16_rn(v - __bfloat162float(h));
    g_Wh[idx] = h; g_Wl[idx] = l;
}

// ---------------------------------------------------------------------------
// CSR build
__global__ void zero_cnt_kernel() {
    int i = blockIdx.x * blockDim.x + threadIdx.x;
    if (i < NN) g_cnt[i] = 0;
}
__global__ void hist_kernel(const int* __restrict__ dst) {
    int e = blockIdx.x * blockDim.x + threadIdx.x;
    if (e < NE) atomicAdd(&g_cnt[dst[e]], 1);
}
// Block-level scan: warp shfl scan + single smem round. 1024 threads.
__global__ void scan1_kernel() {
    __shared__ int wsum[32];
    int tid = threadIdx.x, lane = tid & 31, wid = tid >> 5;
    int i = blockIdx.x * 1024 + tid;
    int v = (i < NN) ? g_cnt[i] : 0;
    int s = warp_iscan(v, lane);
    if (lane == 31) wsum[wid] = s;
    __syncthreads();
    if (wid == 0) {
        int t = wsum[lane];
        int sc = warp_iscan(t, lane);
        wsum[lane] = sc - t;              // exclusive warp offsets
    }
    __syncthreads();
    int incl = s + wsum[wid];
    if (i < NN) g_rs[i] = incl - v;       // exclusive within block
    if (tid == 1023) g_part[blockIdx.x] = incl;
}
// Scan the 49 block partials with shuffles (no serial chain). 64 threads.
__global__ void scan2_kernel(int nblk) {
    __shared__ int w0tot;
    int tid = threadIdx.x, lane = tid & 31, wid = tid >> 5;
    int v = (tid < nblk) ? g_part[tid] : 0;
    int s = warp_iscan(v, lane);
    if (wid == 0 && lane == 31) w0tot = s;
    __syncthreads();
    if (wid == 1) s += w0tot;
    if (tid < nblk) g_part[tid] = s - v;  // exclusive
}
__global__ void scan3_kernel() {
    int tid = threadIdx.x;
    int i = blockIdx.x * 1024 + tid;
    if (i < NN) {
        int v = g_rs[i] + g_part[blockIdx.x];
        g_rs[i] = v;
        g_cur[i] = v;
    }
    if (i == 0) g_rs[NN] = NE;
}
__global__ void fill_kernel(const int* __restrict__ src, const int* __restrict__ dst,
                            const int* __restrict__ rel, const float* __restrict__ w) {
    int e = blockIdx.x * blockDim.x + threadIdx.x;
    if (e >= NE) return;
    int d = dst[e];
    int pos = atomicAdd(&g_cur[d], 1);
    g_ep[pos] = make_int2(src[e] * 8 + rel[e], __float_as_int(w[e]));
}

// ---------------------------------------------------------------------------
// Tensor-core GEMM (mma.sync bf16 split); z written as bf16.
#define AP 72
#define BP 72
#define SM_BIAS 0
#define SM_AH   256
#define SM_AL   (SM_AH + 128 * AP * 2)
#define SM_BH   (SM_AL + 128 * AP * 2)
#define SM_BL   (SM_BH + 64 * BP * 2)
#define SMEM_TOTAL (SM_BL + 64 * BP * 2)   // 55552 B

__global__ __launch_bounds__(256) void gemm_kernel(const float* __restrict__ x,
                                                   const float* __restrict__ b_lin,
                                                   const float* __restrict__ b_self,
                                                   float* __restrict__ out) {
    extern __shared__ char smem[];
    uint32_t sb = smem_u32(smem);
    int t = threadIdx.x, wid = t >> 5, lid = t & 31;
    int m_base = blockIdx.x * 128;

    float* bias = (float*)(smem + SM_BIAS);
    if (t < 64) bias[t] = b_lin[t] + b_self[t];

    for (int f = t; f < 128 * 32; f += 256) {
        int m = f >> 5, kp = f & 31;
        float2 v = make_float2(0.f, 0.f);
        int gm = m_base + m;
        if (gm < NN) v = *(const float2*)&x[gm * DD + kp * 2];
        __nv_bfloat16 hx = __float2bfloat16_rn(v.x);
        __nv_bfloat16 hy = __float2bfloat16_rn(v.y);
        __nv_bfloat16 lx = __float2bfloat16_rn(v.x - __bfloat162float(hx));
        __nv_bfloat16 ly = __float2bfloat16_rn(v.y - __bfloat162float(hy));
        uint32_t hp = (uint32_t)__bfloat16_as_ushort(hx) | ((uint32_t)__bfloat16_as_ushort(hy) << 16);
        uint32_t lp = (uint32_t)__bfloat16_as_ushort(lx) | ((uint32_t)__bfloat16_as_ushort(ly) << 16);
        uint32_t boff = (uint32_t)(m * AP + kp * 2) * 2;
        *(uint32_t*)(smem + SM_AH + boff) = hp;
        *(uint32_t*)(smem + SM_AL + boff) = lp;
    }
    __syncthreads();

    uint32_t a_h[4][4], a_l[4][4];
    {
        int arow = wid * 16 + (lid & 7) + ((lid >> 3) & 1) * 8;
        int acol = (lid >> 4) * 8;
#pragma unroll
        for (int kk = 0; kk < 4; kk++) {
            uint32_t off = (uint32_t)(arow * AP + kk * 16 + acol) * 2;
            ldsm_x4(a_h[kk], sb + SM_AH + off);
            ldsm_x4(a_l[kk], sb + SM_AL + off);
        }
    }

    for (int g = 0; g < 9; g++) {
        __syncthreads();
        for (int f = t; f < 64 * 8; f += 256) {
            int k = f >> 3, jc = f & 7;
            uint4 vh = *(const uint4*)&g_Wh[(g * 64 + k) * 64 + jc * 8];
            uint4 vl = *(const uint4*)&g_Wl[(g * 64 + k) * 64 + jc * 8];
            uint32_t boff = (uint32_t)(k * BP + jc * 8) * 2;
            *(uint4*)(smem + SM_BH + boff) = vh;
            *(uint4*)(smem + SM_BL + boff) = vl;
        }
        __syncthreads();

        float acc[8][4];
#pragma unroll
        for (int n = 0; n < 8; n++)
#pragma unroll
            for (int q = 0; q < 4; q++) acc[n][q] = 0.f;

        int brow_i = (lid & 7) + ((lid >> 3) & 1) * 8;
        int bcol_i = (lid >> 4) * 8;
#pragma unroll
        for (int kk = 0; kk < 4; kk++) {
            uint32_t bfh[16], bfl[16];
#pragma unroll
            for (int tp = 0; tp < 4; tp++) {
                uint32_t off = (uint32_t)((kk * 16 + brow_i) * BP + tp * 16 + bcol_i) * 2;
                ldsm_x4_t(bfh + tp * 4, sb + SM_BH + off);
                ldsm_x4_t(bfl + tp * 4, sb + SM_BL + off);
            }
#pragma unroll
            for (int n = 0; n < 8; n++) {
                int base = (n >> 1) * 4 + (n & 1) * 2;
                mma_bf16(acc[n], a_h[kk], bfh[base], bfh[base + 1]);
                mma_bf16(acc[n], a_h[kk], bfl[base], bfl[base + 1]);
                mma_bf16(acc[n], a_l[kk], bfh[base], bfh[base + 1]);
            }
        }

        int r0 = m_base + wid * 16 + (lid >> 2);
        int r1 = r0 + 8;
        int c0 = (lid & 3) * 2;
        if (g < 8) {
#pragma unroll
            for (int n = 0; n < 8; n++) {
                int col = g * 64 + n * 8 + c0;
                __nv_bfloat162 v0 = __float22bfloat162_rn(make_float2(acc[n][0], acc[n][1]));
                __nv_bfloat162 v1 = __float22bfloat162_rn(make_float2(acc[n][2], acc[n][3]));
                if (r0 < NN) *(__nv_bfloat162*)&g_z[(size_t)r0 * ZC + col] = v0;
                if (r1 < NN) *(__nv_bfloat162*)&g_z[(size_t)r1 * ZC + col] = v1;
            }
        } else {
#pragma unroll
            for (int n = 0; n < 8; n++) {
                int col = n * 8 + c0;
                float2 bs = *(float2*)&bias[col];
                if (r0 < NN) *(float2*)&out[r0 * DD + col] = make_float2(acc[n][0] + bs.x, acc[n][1] + bs.y);
                if (r1 < NN) *(float2*)&out[r1 * DD + col] = make_float2(acc[n][2] + bs.x, acc[n][3] + bs.y);
            }
        }
    }
}

// ---------------------------------------------------------------------------
// Gather: one warp per destination node; z rows are bf16 (128 B per row).
__global__ __launch_bounds__(256) void gather_kernel(float* __restrict__ out) {
    __shared__ float sinv[8][8];
    int t = threadIdx.x, wid = t >> 5, lid = t & 31;
    int node = blockIdx.x * 8 + wid;
    int beg = g_rs[node], end = g_rs[node + 1];

    // Pass 1: per-relation degrees
    float deg8[8];
#pragma unroll
    for (int q = 0; q < 8; q++) deg8[q] = 0.f;
    for (int i = beg + lid; i < end; i += 32) {
        int2 p = g_ep[i];
        int r = p.x & 7;
        float w = __int_as_float(p.y);
#pragma unroll
        for (int q = 0; q < 8; q++) if (r == q) deg8[q] += w;
    }
#pragma unroll
    for (int q = 0; q < 8; q++)
#pragma unroll
        for (int o = 16; o; o >>= 1) deg8[q] += __shfl_xor_sync(0xFFFFFFFFu, deg8[q], o);
    if (lid == 0) {
#pragma unroll
        for (int q = 0; q < 8; q++) sinv[wid][q] = 1.0f / deg8[q];
    }
    __syncwarp();

    // Pass 2: accumulate (w/deg) * z[src,rel]; each lane owns 2 output floats
    float a0 = 0.f, a1 = 0.f;
    int i = beg;
    for (; i + 1 < end; i += 2) {
        int2 p0 = g_ep[i], p1 = g_ep[i + 1];
        __nv_bfloat162 zb0 = *(const __nv_bfloat162*)&g_z[(size_t)p0.x * 64 + lid * 2];
        __nv_bfloat162 zb1 = *(const __nv_bfloat162*)&g_z[(size_t)p1.x * 64 + lid * 2];
        float v0 = __int_as_float(p0.y) * sinv[wid][p0.x & 7];
        float v1 = __int_as_float(p1.y) * sinv[wid][p1.x & 7];
        float2 z0 = __bfloat1622float2(zb0);
        float2 z1 = __bfloat1622float2(zb1);
        a0 += v0 * z0.x + v1 * z1.x;
        a1 += v0 * z0.y + v1 * z1.y;
    }
    if (i < end) {
        int2 p0 = g_ep[i];
        __nv_bfloat162 zb0 = *(const __nv_bfloat162*)&g_z[(size_t)p0.x * 64 + lid * 2];
        float v0 = __int_as_float(p0.y) * sinv[wid][p0.x & 7];
        float2 z0 = __bfloat1622float2(zb0);
        a0 += v0 * z0.x;
        a1 += v0 * z0.y;
    }

    float2 o = *(float2*)&out[node * DD + lid * 2];
    o.x = fmaxf(o.x + a0, 0.f);
    o.y = fmaxf(o.y + a1, 0.f);
    *(float2*)&out[node * DD + lid * 2] = o;
}

// ---------------------------------------------------------------------------
extern "C" void kernel_launch(void* const* d_in, const int* in_sizes, int n_in,
                              void* d_out, int out_size) {
    const float* x      = (const float*)d_in[0];
    const int*   e_src  = (const int*)d_in[1];
    const int*   e_dst  = (const int*)d_in[2];
    const int*   e_rel  = (const int*)d_in[3];
    const float* e_w    = (const float*)d_in[4];
    const float* W_lin  = (const float*)d_in[5];
    const float* b_lin  = (const float*)d_in[6];
    const float* W_self = (const float*)d_in[7];
    const float* b_self = (const float*)d_in[8];
    float* out = (float*)d_out;

    cudaFuncSetAttribute(gemm_kernel, cudaFuncAttributeMaxDynamicSharedMemorySize, SMEM_TOTAL);

    const int SCAN_BLKS = (NN + 1023) / 1024;   // 49
    prep_w_kernel<<<(576 * 64 + 255) / 256, 256>>>(W_lin, W_self);
    zero_cnt_kernel<<<(NN + 255) / 256, 256>>>();
    hist_kernel<<<(NE + 255) / 256, 256>>>(e_dst);
    scan1_kernel<<<SCAN_BLKS, 1024>>>();
    scan2_kernel<<<1, 64>>>(SCAN_BLKS);
    scan3_kernel<<<SCAN_BLKS, 1024>>>();
    fill_kernel<<<(NE + 255) / 256, 256>>>(e_src, e_dst, e_rel, e_w);
    gemm_kernel<<<(NN + 127) / 128, 256, SMEM_TOTAL>>>(x, b_lin, b_self, out);
    gather_kernel<<<NN / 8, 256>>>(out);
}

// round 6
// speedup vs baseline: 1.4067x; 1.0093x over previous
#include <cuda_runtime.h>
#include <cuda_bf16.h>
#include <cuda_fp16.h>
#include <cstdint>

#define NN 50000
#define NE 1000000
#define DD 64
#define RR 8
#define ZC 512

// Scratch (allocation-free rule)
__device__ __half g_z[(size_t)NN * ZC];   // 51.2 MB, fp16, L2-resident
__device__ __nv_bfloat16 g_Wh[576 * 64];
__device__ __nv_bfloat16 g_Wl[576 * 64];
__device__ int  g_cnt[NN];
__device__ int  g_rs[NN];       // scan result; advanced to segment END by fill
__device__ int  g_part[64];
__device__ int2 g_ep[NE];       // packed: {src*8+rel, w bits}

// ---------------------------------------------------------------------------
__device__ __forceinline__ uint32_t smem_u32(const void* p) {
    uint32_t a;
    asm("{ .reg .u64 t; cvta.to.shared.u64 t, %1; cvt.u32.u64 %0, t; }" : "=r"(a) : "l"(p));
    return a;
}
__device__ __forceinline__ void ldsm_x4(uint32_t* r, uint32_t addr) {
    asm volatile("ldmatrix.sync.aligned.m8n8.x4.shared.b16 {%0,%1,%2,%3}, [%4];"
                 : "=r"(r[0]), "=r"(r[1]), "=r"(r[2]), "=r"(r[3]) : "r"(addr));
}
__device__ __forceinline__ void ldsm_x4_t(uint32_t* r, uint32_t addr) {
    asm volatile("ldmatrix.sync.aligned.m8n8.x4.trans.shared.b16 {%0,%1,%2,%3}, [%4];"
                 : "=r"(r[0]), "=r"(r[1]), "=r"(r[2]), "=r"(r[3]) : "r"(addr));
}
__device__ __forceinline__ void mma_bf16(float* c, const uint32_t* a, uint32_t b0, uint32_t b1) {
    asm volatile("mma.sync.aligned.m16n8k16.row.col.f32.bf16.bf16.f32 "
                 "{%0,%1,%2,%3}, {%4,%5,%6,%7}, {%8,%9}, {%0,%1,%2,%3};"
                 : "+f"(c[0]), "+f"(c[1]), "+f"(c[2]), "+f"(c[3])
                 : "r"(a[0]), "r"(a[1]), "r"(a[2]), "r"(a[3]), "r"(b0), "r"(b1));
}
__device__ __forceinline__ int warp_iscan(int v, int lane) {
#pragma unroll
    for (int off = 1; off < 32; off <<= 1) {
        int t = __shfl_up_sync(0xFFFFFFFFu, v, off);
        if (lane >= off) v += t;
    }
    return v;
}

// ---------------------------------------------------------------------------
__global__ void prep_w_kernel(const float* __restrict__ Wlin, const float* __restrict__ Wself) {
    int idx = blockIdx.x * blockDim.x + threadIdx.x;
    if (idx >= 576 * 64) return;
    float v = (idx < 512 * 64) ? Wlin[idx] : Wself[idx - 512 * 64];
    __nv_bfloat16 h = __float2bfloat16_rn(v);
    __nv_bfloat16 l = __float2bfloat16_rn(v - __bfloat162float(h));
    g_Wh[idx] = h; g_Wl[idx] = l;
}

// ---------------------------------------------------------------------------
// CSR build
__global__ void zero_cnt_kernel() {
    int i = blockIdx.x * blockDim.x + threadIdx.x;
    if (i < NN) g_cnt[i] = 0;
}
__global__ void hist_kernel(const int* __restrict__ dst) {
    int e = blockIdx.x * blockDim.x + threadIdx.x;
    if (e < NE) atomicAdd(&g_cnt[dst[e]], 1);
}
__global__ void scan1_kernel() {
    __shared__ int wsum[32];
    int tid = threadIdx.x, lane = tid & 31, wid = tid >> 5;
    int i = blockIdx.x * 1024 + tid;
    int v = (i < NN) ? g_cnt[i] : 0;
    int s = warp_iscan(v, lane);
    if (lane == 31) wsum[wid] = s;
    __syncthreads();
    if (wid == 0) {
        int t = wsum[lane];
        int sc = warp_iscan(t, lane);
        wsum[lane] = sc - t;
    }
    __syncthreads();
    int incl = s + wsum[wid];
    if (i < NN) g_rs[i] = incl - v;
    if (tid == 1023) g_part[blockIdx.x] = incl;
}
__global__ void scan2_kernel(int nblk) {
    __shared__ int w0tot;
    int tid = threadIdx.x, lane = tid & 31, wid = tid >> 5;
    int v = (tid < nblk) ? g_part[tid] : 0;
    int s = warp_iscan(v, lane);
    if (wid == 0 && lane == 31) w0tot = s;
    __syncthreads();
    if (wid == 1) s += w0tot;
    if (tid < nblk) g_part[tid] = s - v;
}
__global__ void scan3_kernel() {
    int tid = threadIdx.x;
    int i = blockIdx.x * 1024 + tid;
    if (i < NN) g_rs[i] += g_part[blockIdx.x];
}
// fill advances g_rs[d] itself; afterwards g_rs[d] == segment end.
__global__ void fill_kernel(const int* __restrict__ src, const int* __restrict__ dst,
                            const int* __restrict__ rel, const float* __restrict__ w) {
    int e = blockIdx.x * blockDim.x + threadIdx.x;
    if (e >= NE) return;
    int d = dst[e];
    int pos = atomicAdd(&g_rs[d], 1);
    g_ep[pos] = make_int2(src[e] * 8 + rel[e], __float_as_int(w[e]));
}

// ---------------------------------------------------------------------------
// Tensor-core GEMM (mma.sync bf16 split); z written as fp16.
#define AP 72
#define BP 72
#define SM_BIAS 0
#define SM_AH   256
#define SM_AL   (SM_AH + 128 * AP * 2)
#define SM_BH   (SM_AL + 128 * AP * 2)
#define SM_BL   (SM_BH + 64 * BP * 2)
#define SMEM_TOTAL (SM_BL + 64 * BP * 2)   // 55552 B

__global__ __launch_bounds__(256) void gemm_kernel(const float* __restrict__ x,
                                                   const float* __restrict__ b_lin,
                                                   const float* __restrict__ b_self,
                                                   float* __restrict__ out) {
    extern __shared__ char smem[];
    uint32_t sb = smem_u32(smem);
    int t = threadIdx.x, wid = t >> 5, lid = t & 31;
    int m_base = blockIdx.x * 128;

    float* bias = (float*)(smem + SM_BIAS);
    if (t < 64) bias[t] = b_lin[t] + b_self[t];

    for (int f = t; f < 128 * 32; f += 256) {
        int m = f >> 5, kp = f & 31;
        float2 v = make_float2(0.f, 0.f);
        int gm = m_base + m;
        if (gm < NN) v = *(const float2*)&x[gm * DD + kp * 2];
        __nv_bfloat16 hx = __float2bfloat16_rn(v.x);
        __nv_bfloat16 hy = __float2bfloat16_rn(v.y);
        __nv_bfloat16 lx = __float2bfloat16_rn(v.x - __bfloat162float(hx));
        __nv_bfloat16 ly = __float2bfloat16_rn(v.y - __bfloat162float(hy));
        uint32_t hp = (uint32_t)__bfloat16_as_ushort(hx) | ((uint32_t)__bfloat16_as_ushort(hy) << 16);
        uint32_t lp = (uint32_t)__bfloat16_as_ushort(lx) | ((uint32_t)__bfloat16_as_ushort(ly) << 16);
        uint32_t boff = (uint32_t)(m * AP + kp * 2) * 2;
        *(uint32_t*)(smem + SM_AH + boff) = hp;
        *(uint32_t*)(smem + SM_AL + boff) = lp;
    }
    __syncthreads();

    uint32_t a_h[4][4], a_l[4][4];
    {
        int arow = wid * 16 + (lid & 7) + ((lid >> 3) & 1) * 8;
        int acol = (lid >> 4) * 8;
#pragma unroll
        for (int kk = 0; kk < 4; kk++) {
            uint32_t off = (uint32_t)(arow * AP + kk * 16 + acol) * 2;
            ldsm_x4(a_h[kk], sb + SM_AH + off);
            ldsm_x4(a_l[kk], sb + SM_AL + off);
        }
    }

    for (int g = 0; g < 9; g++) {
        __syncthreads();
        for (int f = t; f < 64 * 8; f += 256) {
            int k = f >> 3, jc = f & 7;
            uint4 vh = *(const uint4*)&g_Wh[(g * 64 + k) * 64 + jc * 8];
            uint4 vl = *(const uint4*)&g_Wl[(g * 64 + k) * 64 + jc * 8];
            uint32_t boff = (uint32_t)(k * BP + jc * 8) * 2;
            *(uint4*)(smem + SM_BH + boff) = vh;
            *(uint4*)(smem + SM_BL + boff) = vl;
        }
        __syncthreads();

        float acc[8][4];
#pragma unroll
        for (int n = 0; n < 8; n++)
#pragma unroll
            for (int q = 0; q < 4; q++) acc[n][q] = 0.f;

        int brow_i = (lid & 7) + ((lid >> 3) & 1) * 8;
        int bcol_i = (lid >> 4) * 8;
#pragma unroll
        for (int kk = 0; kk < 4; kk++) {
            uint32_t bfh[16], bfl[16];
#pragma unroll
            for (int tp = 0; tp < 4; tp++) {
                uint32_t off = (uint32_t)((kk * 16 + brow_i) * BP + tp * 16 + bcol_i) * 2;
                ldsm_x4_t(bfh + tp * 4, sb + SM_BH + off);
                ldsm_x4_t(bfl + tp * 4, sb + SM_BL + off);
            }
#pragma unroll
            for (int n = 0; n < 8; n++) {
                int base = (n >> 1) * 4 + (n & 1) * 2;
                mma_bf16(acc[n], a_h[kk], bfh[base], bfh[base + 1]);
                mma_bf16(acc[n], a_h[kk], bfl[base], bfl[base + 1]);
                mma_bf16(acc[n], a_l[kk], bfh[base], bfh[base + 1]);
            }
        }

        int r0 = m_base + wid * 16 + (lid >> 2);
        int r1 = r0 + 8;
        int c0 = (lid & 3) * 2;
        if (g < 8) {
#pragma unroll
            for (int n = 0; n < 8; n++) {
                int col = g * 64 + n * 8 + c0;
                __half2 v0 = __float22half2_rn(make_float2(acc[n][0], acc[n][1]));
                __half2 v1 = __float22half2_rn(make_float2(acc[n][2], acc[n][3]));
                if (r0 < NN) *(__half2*)&g_z[(size_t)r0 * ZC + col] = v0;
                if (r1 < NN) *(__half2*)&g_z[(size_t)r1 * ZC + col] = v1;
            }
        } else {
#pragma unroll
            for (int n = 0; n < 8; n++) {
                int col = n * 8 + c0;
                float2 bs = *(float2*)&bias[col];
                if (r0 < NN) *(float2*)&out[r0 * DD + col] = make_float2(acc[n][0] + bs.x, acc[n][1] + bs.y);
                if (r1 < NN) *(float2*)&out[r1 * DD + col] = make_float2(acc[n][2] + bs.x, acc[n][3] + bs.y);
            }
        }
    }
}

// ---------------------------------------------------------------------------
// Gather: one warp per destination node; z rows fp16 (128 B). Unroll x4 for MLP.
__global__ __launch_bounds__(256) void gather_kernel(float* __restrict__ out) {
    __shared__ float sinv[8][8];
    int t = threadIdx.x, wid = t >> 5, lid = t & 31;
    int node = blockIdx.x * 8 + wid;
    int end = g_rs[node];                 // post-fill: segment end
    int beg = end - g_cnt[node];

    // Pass 1: per-relation degrees
    float deg8[8];
#pragma unroll
    for (int q = 0; q < 8; q++) deg8[q] = 0.f;
    for (int i = beg + lid; i < end; i += 32) {
        int2 p = g_ep[i];
        int r = p.x & 7;
        float w = __int_as_float(p.y);
#pragma unroll
        for (int q = 0; q < 8; q++) if (r == q) deg8[q] += w;
    }
#pragma unroll
    for (int q = 0; q < 8; q++)
#pragma unroll
        for (int o = 16; o; o >>= 1) deg8[q] += __shfl_xor_sync(0xFFFFFFFFu, deg8[q], o);
    if (lid == 0) {
#pragma unroll
        for (int q = 0; q < 8; q++) sinv[wid][q] = 1.0f / deg8[q];
    }
    __syncwarp();

    // Pass 2: accumulate (w/deg)*z[src,rel]; lane owns 2 floats; unroll x4
    float a0 = 0.f, a1 = 0.f;
    int i = beg;
    for (; i + 3 < end; i += 4) {
        int2 p0 = g_ep[i], p1 = g_ep[i + 1], p2 = g_ep[i + 2], p3 = g_ep[i + 3];
        __half2 zb0 = *(const __half2*)&g_z[(size_t)p0.x * 64 + lid * 2];
        __half2 zb1 = *(const __half2*)&g_z[(size_t)p1.x * 64 + lid * 2];
        __half2 zb2 = *(const __half2*)&g_z[(size_t)p2.x * 64 + lid * 2];
        __half2 zb3 = *(const __half2*)&g_z[(size_t)p3.x * 64 + lid * 2];
        float v0 = __int_as_float(p0.y) * sinv[wid][p0.x & 7];
        float v1 = __int_as_float(p1.y) * sinv[wid][p1.x & 7];
        float v2 = __int_as_float(p2.y) * sinv[wid][p2.x & 7];
        float v3 = __int_as_float(p3.y) * sinv[wid][p3.x & 7];
        float2 z0 = __half22float2(zb0);
        float2 z1 = __half22float2(zb1);
        float2 z2 = __half22float2(zb2);
        float2 z3 = __half22float2(zb3);
        a0 += v0 * z0.x + v1 * z1.x + v2 * z2.x + v3 * z3.x;
        a1 += v0 * z0.y + v1 * z1.y + v2 * z2.y + v3 * z3.y;
    }
    for (; i < end; i++) {
        int2 p0 = g_ep[i];
        __half2 zb0 = *(const __half2*)&g_z[(size_t)p0.x * 64 + lid * 2];
        float v0 = __int_as_float(p0.y) * sinv[wid][p0.x & 7];
        float2 z0 = __half22float2(zb0);
        a0 += v0 * z0.x;
        a1 += v0 * z0.y;
    }

    float2 o = *(float2*)&out[node * DD + lid * 2];
    o.x = fmaxf(o.x + a0, 0.f);
    o.y = fmaxf(o.y + a1, 0.f);
    *(float2*)&out[node * DD + lid * 2] = o;
}

// ---------------------------------------------------------------------------
extern "C" void kernel_launch(void* const* d_in, const int* in_sizes, int n_in,
                              void* d_out, int out_size) {
    const float* x      = (const float*)d_in[0];
    const int*   e_src  = (const int*)d_in[1];
    const int*   e_dst  = (const int*)d_in[2];
    const int*   e_rel  = (const int*)d_in[3];
    const float* e_w    = (const float*)d_in[4];
    const float* W_lin  = (const float*)d_in[5];
    const float* b_lin  = (const float*)d_in[6];
    const float* W_self = (const float*)d_in[7];
    const float* b_self = (const float*)d_in[8];
    float* out = (float*)d_out;

    cudaFuncSetAttribute(gemm_kernel, cudaFuncAttributeMaxDynamicSharedMemorySize, SMEM_TOTAL);

    const int SCAN_BLKS = (NN + 1023) / 1024;   // 49
    // Order chosen so the profiler's fixed capture slot lands on gemm_kernel.
    zero_cnt_kernel<<<(NN + 255) / 256, 256>>>();
    hist_kernel<<<(NE + 255) / 256, 256>>>(e_dst);
    prep_w_kernel<<<(576 * 64 + 255) / 256, 256>>>(W_lin, W_self);
    gemm_kernel<<<(NN + 127) / 128, 256, SMEM_TOTAL>>>(x, b_lin, b_self, out);
    scan1_kernel<<<SCAN_BLKS, 1024>>>();
    scan2_kernel<<<1, 64>>>(SCAN_BLKS);
    scan3_kernel<<<SCAN_BLKS, 1024>>>();
    fill_kernel<<<(NE + 255) / 256, 256>>>(e_src, e_dst, e_rel, e_w);
    gather_kernel<<<NN / 8, 256>>>(out);
}